// round 13
// baseline (speedup 1.0000x reference)
#include <cuda_runtime.h>

// Problem constants
#define T_STEPS 500
#define BATCH   1024
#define NDIM    256
#define ALPHA_F 0.995f   // 1 - 0.05/10
#define VTH_F   1.0f

#define TPB        256
#define C_BLOCKS   4                          // consumer blocks (first in grid)
#define ROWS_PB    8                          // 1 row/warp, 8 warps/block (R1 shape)
#define N_ROWS     (T_STEPS * BATCH)          // 512000
#define P_BLOCKS   (N_ROWS / ROWS_PB)         // 64000 one-shot producer blocks

#define CHUNK_T    20                         // consumer batching only
#define N_CHUNKS   (T_STEPS / CHUNK_T)        // 25

#define SENTINEL 0xFFFFFFFFu   // NaN bits unreachable by finite FMA chains

// Scratch: per-(t,b) input currents (2 MB, stays L2-resident).
// VALUE doubles as the ready flag: init poisons, producers overwrite,
// consumers poll with ld.relaxed.gpu until bits != SENTINEL.
__device__ float g_s[T_STEPS * BATCH];

// Memory-model load at GPU scope: guaranteed to observe the L2 coherence
// point (unlike ld.global.cg, which leaked stale sentinels in R12).
__device__ __forceinline__ unsigned ld_relaxed_gpu_u32(const float* p) {
    unsigned v;
    asm volatile("ld.relaxed.gpu.global.u32 %0, [%1];" : "=r"(v) : "l"(p) : "memory");
    return v;
}

// ---------------------------------------------------------------------------
// Kernel 0: poison g_s (runs every graph replay; ~1us)
// ---------------------------------------------------------------------------
__global__ void __launch_bounds__(TPB) lif_init_kernel()
{
    uint4* p = reinterpret_cast<uint4*>(g_s);
    p[blockIdx.x * TPB + threadIdx.x] =
        make_uint4(SENTINEL, SENTINEL, SENTINEL, SENTINEL);
}

// ---------------------------------------------------------------------------
// Kernel 1: fused. Producers carry ZERO synchronization — they are the
// standalone roofline GEMV (89% DRAM measured) as one-shot blocks.
// ---------------------------------------------------------------------------
__global__ void __launch_bounds__(TPB) lif_fused_kernel(
    const float* __restrict__ x,      // [T, B, N]
    const float* __restrict__ w,      // [N]
    float* __restrict__ out)          // [2, T, B]  (v then z)
{
    const int tid = threadIdx.x;

    if (blockIdx.x >= C_BLOCKS) {
        // ============ PRODUCER (pure R1 body, no sync, no loops) ============
        const int warp = tid >> 5;
        const int lane = tid & 31;
        const long long row = (long long)(blockIdx.x - C_BLOCKS) * ROWS_PB + warp;

        const float4* wv = reinterpret_cast<const float4*>(w);
        const float4 w0 = wv[lane];          // w: 1KB, L1/L2 resident
        const float4 w1 = wv[lane + 32];

        const float4* xr = reinterpret_cast<const float4*>(x + row * NDIM);
        const float4 a0 = xr[lane];
        const float4 a1 = xr[lane + 32];

        float acc = a0.x * w0.x + a0.y * w0.y + a0.z * w0.z + a0.w * w0.w
                  + a1.x * w1.x + a1.y * w1.y + a1.z * w1.z + a1.w * w1.w;

        #pragma unroll
        for (int off = 16; off > 0; off >>= 1)
            acc += __shfl_xor_sync(0xffffffffu, acc, off);

        if (lane == 0) g_s[row] = acc;   // plain store; the value IS the flag
        // exit — scheduler refills the slot with a fresh load-issuing block
    } else {
        // ================= CONSUMER (persistent, 25 chunks) =================
        const int b = blockIdx.x * TPB + tid;   // 0..1023
        float* __restrict__ vout = out;                               // [T, B]
        float* __restrict__ zout = out + (long long)T_STEPS * BATCH;  // [T, B]

        float v = 0.0f, z = 0.0f;

        #pragma unroll 1
        for (int c = 0; c < N_CHUNKS; ++c) {
            const int tbase = c * CHUNK_T;

            // batch-issue 20 polls, then verify/spin per word
            unsigned bits[CHUNK_T];
            #pragma unroll
            for (int i = 0; i < CHUNK_T; ++i)
                bits[i] = ld_relaxed_gpu_u32(&g_s[(tbase + i) * BATCH + b]);

            #pragma unroll
            for (int i = 0; i < CHUNK_T; ++i) {
                while (bits[i] == SENTINEL)
                    bits[i] = ld_relaxed_gpu_u32(&g_s[(tbase + i) * BATCH + b]);
            }

            #pragma unroll
            for (int i = 0; i < CHUNK_T; ++i) {
                const float s = __uint_as_float(bits[i]);
                v = ALPHA_F * v + s - z;
                z = (v > VTH_F) ? 1.0f : 0.0f;
                const int t = tbase + i;
                vout[(long long)t * BATCH + b] = v;
                zout[(long long)t * BATCH + b] = z;
            }
        }
    }
}

// ---------------------------------------------------------------------------
extern "C" void kernel_launch(void* const* d_in, const int* in_sizes, int n_in,
                              void* d_out, int out_size)
{
    const float* x = (const float*)d_in[0];   // [T, B, N] fp32
    const float* w = (const float*)d_in[1];   // [N] fp32
    float* out = (float*)d_out;               // [2, T, B] fp32

    lif_init_kernel<<<N_ROWS / (TPB * 4), TPB>>>();
    lif_fused_kernel<<<C_BLOCKS + P_BLOCKS, TPB>>>(x, w, out);
}

// round 14
// speedup vs baseline: 1.3209x; 1.3209x over previous
#include <cuda_runtime.h>

// Problem constants
#define T_STEPS 500
#define BATCH   1024
#define NDIM    256
#define ALPHA_F 0.995f   // 1 - 0.05/10
#define VTH_F   1.0f

#define TPB        256
#define C_BLOCKS   4                          // consumer blocks (first in grid)
#define ROWS_PB    8                          // 1 row/warp, 8 warps/block (R1 shape)
#define N_ROWS     (T_STEPS * BATCH)          // 512000
#define P_BLOCKS   (N_ROWS / ROWS_PB)         // 64000 one-shot producer blocks

#define GROUP      4                          // consumer double-buffer depth (low regs!)

#define SENTINEL 0xFFFFFFFFu   // NaN bits unreachable by finite FMA chains

// Scratch: per-(t,b) input currents (2 MB, stays L2-resident).
// VALUE doubles as the ready flag: init poisons, producers overwrite,
// consumers poll with ld.relaxed.gpu until bits != SENTINEL.
__device__ float g_s[T_STEPS * BATCH];

// Memory-model load at GPU scope: guaranteed to observe the L2 coherence
// point (ld.global.cg leaked stale sentinels in R12; this passed in R13).
__device__ __forceinline__ unsigned ld_relaxed_gpu_u32(const float* p) {
    unsigned v;
    asm volatile("ld.relaxed.gpu.global.u32 %0, [%1];" : "=r"(v) : "l"(p) : "memory");
    return v;
}

// ---------------------------------------------------------------------------
// Kernel 0: poison g_s (runs every graph replay; ~1us)
// ---------------------------------------------------------------------------
__global__ void __launch_bounds__(TPB) lif_init_kernel()
{
    uint4* p = reinterpret_cast<uint4*>(g_s);
    p[blockIdx.x * TPB + threadIdx.x] =
        make_uint4(SENTINEL, SENTINEL, SENTINEL, SENTINEL);
}

// ---------------------------------------------------------------------------
// Kernel 1: fused, zero producer-side synchronization.
// __launch_bounds__(256, 6): cap regs at 40 so the consumer branch cannot
// inflate producer occupancy (R13 failure: unified reg alloc -> regs=80,
// occ=25%, DRAM=42%). Producer body fits in ~30 regs.
// ---------------------------------------------------------------------------
__global__ void __launch_bounds__(TPB, 6) lif_fused_kernel(
    const float* __restrict__ x,      // [T, B, N]
    const float* __restrict__ w,      // [N]
    float* __restrict__ out)          // [2, T, B]  (v then z)
{
    const int tid = threadIdx.x;

    if (blockIdx.x >= C_BLOCKS) {
        // ============ PRODUCER (pure R1 body, no sync, no loops) ============
        const int warp = tid >> 5;
        const int lane = tid & 31;
        const long long row = (long long)(blockIdx.x - C_BLOCKS) * ROWS_PB + warp;

        const float4* wv = reinterpret_cast<const float4*>(w);
        const float4 w0 = wv[lane];          // w: 1KB, L1/L2 resident
        const float4 w1 = wv[lane + 32];

        const float4* xr = reinterpret_cast<const float4*>(x + row * NDIM);
        const float4 a0 = xr[lane];
        const float4 a1 = xr[lane + 32];

        float acc = a0.x * w0.x + a0.y * w0.y + a0.z * w0.z + a0.w * w0.w
                  + a1.x * w1.x + a1.y * w1.y + a1.z * w1.z + a1.w * w1.w;

        #pragma unroll
        for (int off = 16; off > 0; off >>= 1)
            acc += __shfl_xor_sync(0xffffffffu, acc, off);

        if (lane == 0) g_s[row] = acc;   // plain store; the value IS the flag
        // exit — scheduler refills the slot with a fresh load-issuing block
    } else {
        // ========== CONSUMER (persistent; 4-deep double buffer, ~28 regs) ==========
        const int b = blockIdx.x * TPB + tid;   // 0..1023
        float* __restrict__ vout = out;                               // [T, B]
        float* __restrict__ zout = out + (long long)T_STEPS * BATCH;  // [T, B]

        float v = 0.0f, z = 0.0f;
        unsigned cur[GROUP], nxt[GROUP];

        #pragma unroll
        for (int i = 0; i < GROUP; ++i)
            cur[i] = ld_relaxed_gpu_u32(&g_s[i * BATCH + b]);

        #pragma unroll 1
        for (int t = 0; t < T_STEPS; t += GROUP) {
            const int tn = t + GROUP;
            if (tn < T_STEPS) {
                #pragma unroll
                for (int i = 0; i < GROUP; ++i)
                    nxt[i] = ld_relaxed_gpu_u32(&g_s[(tn + i) * BATCH + b]);
            }

            #pragma unroll
            for (int i = 0; i < GROUP; ++i) {
                while (cur[i] == SENTINEL)          // rarely taken: consumer trails
                    cur[i] = ld_relaxed_gpu_u32(&g_s[(t + i) * BATCH + b]);
                const float s = __uint_as_float(cur[i]);
                v = ALPHA_F * v + s - z;
                z = (v > VTH_F) ? 1.0f : 0.0f;
                vout[(long long)(t + i) * BATCH + b] = v;
                zout[(long long)(t + i) * BATCH + b] = z;
            }

            #pragma unroll
            for (int i = 0; i < GROUP; ++i)
                cur[i] = nxt[i];
        }
    }
}

// ---------------------------------------------------------------------------
extern "C" void kernel_launch(void* const* d_in, const int* in_sizes, int n_in,
                              void* d_out, int out_size)
{
    const float* x = (const float*)d_in[0];   // [T, B, N] fp32
    const float* w = (const float*)d_in[1];   // [N] fp32
    float* out = (float*)d_out;               // [2, T, B] fp32

    lif_init_kernel<<<N_ROWS / (TPB * 4), TPB>>>();
    lif_fused_kernel<<<C_BLOCKS + P_BLOCKS, TPB>>>(x, w, out);
}